// round 10
// baseline (speedup 1.0000x reference)
#include <cuda_runtime.h>
#include <cuda_bf16.h>
#include <cstdint>

#define BB    4
#define LQ    256
#define LK    2048
#define HIDD  1024
#define NH    16
#define DD    64
#define QT    16                     /* q rows per CTA */
#define NT    256                    /* threads per CTA */
#define NCH   16                     /* chunks of 128 k */

#define CENTER_C      72.21632f
#define INV_SCALING_C 0.14662718f

/* smem layout (floats): 2 stages of 10496; K rows stride 68f (272B),
   V rows stride 132f (528B), e-region at +8448 (16 x 128f). */
#define STGF   10496
#define VOFF   0
#define EOFF   8448
#define QOFF   20992
#define DOFF   22016
#define IOFF   22080
#define POFF   22096
#define MBOFF  (22160 * 4)           /* byte offset of mbar[2] */
#define SMEMF  (22160 * 4 + 16)

typedef unsigned long long u64;
#define ABSM 0x7FFFFFFF7FFFFFFFULL

__device__ float g_VT[(size_t)BB * NH * DD * LK];   // V transposed [b,h,d,k]

__device__ __forceinline__ u64 fadd2(u64 a, u64 b) {
    u64 r; asm("add.rn.f32x2 %0, %1, %2;" : "=l"(r) : "l"(a), "l"(b)); return r;
}
__device__ __forceinline__ u64 ffma2(u64 a, u64 b, u64 c) {
    u64 r; asm("fma.rn.f32x2 %0, %1, %2, %3;" : "=l"(r) : "l"(a), "l"(b), "l"(c)); return r;
}
__device__ __forceinline__ float2 upk2(u64 a) {
    float2 f; asm("mov.b64 {%0, %1}, %2;" : "=f"(f.x), "=f"(f.y) : "l"(a)); return f;
}
__device__ __forceinline__ void bulk_cp(uint32_t dst, const void* src,
                                        uint32_t bytes, uint32_t mbar) {
    asm volatile(
        "cp.async.bulk.shared::cluster.global.mbarrier::complete_tx::bytes "
        "[%0], [%1], %2, [%3];"
        :: "r"(dst), "l"(src), "r"(bytes), "r"(mbar) : "memory");
}
#define MBAR_INIT(a, n) \
    asm volatile("mbarrier.init.shared.b64 [%0], %1;" :: "r"(a), "r"(n) : "memory")
#define MBAR_EXPECT(a, tx) \
    asm volatile("mbarrier.arrive.expect_tx.shared.b64 _, [%0], %1;" :: "r"(a), "r"(tx) : "memory")
#define MBAR_WAIT(a, ph) do {                                                  \
    uint32_t _m = (a), _p = (ph), _d;                                          \
    asm volatile("{\n\t.reg .pred p;\n\t"                                      \
        "mbarrier.try_wait.parity.acquire.cta.shared::cta.b64 p, [%1], %2;\n\t"\
        "selp.b32 %0, 1, 0, p;\n\t}"                                           \
        : "=r"(_d) : "r"(_m), "r"(_p) : "memory");                             \
    if (!_d) {                                                                 \
        asm volatile("{\n\t.reg .pred P1;\n\t"                                 \
        "W_%=:\n\t"                                                            \
        "mbarrier.try_wait.parity.acquire.cta.shared::cta.b64 P1, [%0], %1, 0x989680;\n\t" \
        "@P1 bra.uni D_%=;\n\t"                                                \
        "bra.uni W_%=;\n\t"                                                    \
        "D_%=:\n\t}" :: "r"(_m), "r"(_p) : "memory");                          \
    }                                                                          \
} while (0)

// ---------------------------------------------------------------------------
// Kernel 0: transpose V -> VT[b,h,d,k].
// ---------------------------------------------------------------------------
__global__ __launch_bounds__(256) void k_vtrans(const float* __restrict__ Vg)
{
    __shared__ float t[64][65];
    const int bh = blockIdx.y, b = bh >> 4, h = bh & 15;
    const int k0 = blockIdx.x * 64;
    const int tid = threadIdx.x;
    #pragma unroll
    for (int r = 0; r < 4; r++) {
        int i = tid + 256 * r; int kr = i >> 4, g = i & 15;
        float4 v = *(const float4*)(Vg + ((size_t)(b * LK + k0 + kr)) * HIDD + h * DD + 4 * g);
        t[kr][4 * g + 0] = v.x; t[kr][4 * g + 1] = v.y;
        t[kr][4 * g + 2] = v.z; t[kr][4 * g + 3] = v.w;
    }
    __syncthreads();
    #pragma unroll
    for (int r = 0; r < 4; r++) {
        int i = tid + 256 * r; int d = i >> 4, g = i & 15;
        float4 o = make_float4(t[4 * g + 0][d], t[4 * g + 1][d], t[4 * g + 2][d], t[4 * g + 3][d]);
        *(float4*)(g_VT + ((size_t)(bh * DD + d)) * LK + k0 + 4 * g) = o;
    }
}

// ---------------------------------------------------------------------------
// Fused kernel: R8 decomposition (kg in 4 x qg in 2), cp.async.bulk staging.
// ---------------------------------------------------------------------------
__global__ __launch_bounds__(NT, 2) void k_fused(
    const float* __restrict__ Qg, const float* __restrict__ Kg,
    const float* __restrict__ diag,
    float* __restrict__ attn, float* __restrict__ out0)
{
    extern __shared__ float smem[];
    float* qbuf = smem + QOFF;
    float* dbuf = smem + DOFF;
    float* invs = smem + IOFF;
    float* part = smem + POFF;

    const int b  = blockIdx.z, h = blockIdx.y;
    const int q0 = blockIdx.x * QT;
    const int tid = threadIdx.x, w = tid >> 5, lane = tid & 31;
    const int kg = w & 3, qg = w >> 2;          // k-quarter (32k), 8 q rows
    const uint32_t sbase = (uint32_t)__cvta_generic_to_shared(smem);
    const uint32_t mb0 = sbase + MBOFF, mb1 = sbase + MBOFF + 8;

    const size_t arow0 = (((size_t)(b * NH + h)) * LQ + q0) * (size_t)LK;
    const float* kgsrc = Kg + (size_t)b * LK * HIDD + h * DD;

    // ---- prologue --------------------------------------------------------
    if (tid == 0) { MBAR_INIT(mb0, 1); MBAR_INIT(mb1, 1); }
    if (tid < 16)
        ((float4*)dbuf)[tid] = ((const float4*)(diag + h * DD))[tid];
    {
        int qr = tid >> 4, g = tid & 15;        // 16 rows x 16 f4, negated
        float4 v = ((const float4*)(Qg + ((size_t)(b * LQ + q0 + qr)) * HIDD + h * DD))[g];
        ((float4*)qbuf)[qr * 16 + g] = make_float4(-v.x, -v.y, -v.z, -v.w);
    }
    __syncthreads();                            // mbar init visible

    // issue K chunk 0 into stage 0 (128 rows x 256B, padded stride 272B)
    if (tid == 0) MBAR_EXPECT(mb0, 32768u);
    if (tid < 128)
        bulk_cp(sbase + (uint32_t)tid * 272u, kgsrc + (size_t)tid * HIDD, 256u, mb0);

    const ulonglong2* qb2 = (const ulonglong2*)qbuf;
    const ulonglong2* db2 = (const ulonglong2*)dbuf;
    float sume[8] = {0.f, 0.f, 0.f, 0.f, 0.f, 0.f, 0.f, 0.f};
    const int krowf = (kg * 32 + lane) * 68;    // float offset of this lane's K row

    // ==== Phase 1: distance -> e -> attn (unnormalized) ===================
    for (int c = 0; c < NCH; c++) {
        MBAR_WAIT((c & 1) ? mb1 : mb0, (c >> 1) & 1);
        __syncthreads();          // all done with the other stage

        if (c + 1 < NCH) {
            uint32_t mbn = ((c + 1) & 1) ? mb1 : mb0;
            uint32_t dstb = sbase + (uint32_t)(((c + 1) & 1) * STGF * 4);
            if (tid == 0) MBAR_EXPECT(mbn, 32768u);
            if (tid < 128)
                bulk_cp(dstb + (uint32_t)tid * 272u,
                        kgsrc + (size_t)((c + 1) * 128 + tid) * HIDD, 256u, mbn);
        }

        const float* stg = smem + (c & 1) * STGF;
        ulonglong2 kvr[16];
        #pragma unroll
        for (int g = 0; g < 16; g++)
            kvr[g] = *(const ulonglong2*)(stg + krowf + g * 4);

        u64 acc[8];
        #pragma unroll
        for (int q = 0; q < 8; q++) acc[q] = 0ull;

        #pragma unroll
        for (int g = 0; g < 16; g++) {
            ulonglong2 dv = db2[g];                              // broadcast
            #pragma unroll
            for (int q = 0; q < 8; q++) {
                ulonglong2 qv = qb2[(qg * 8 + q) * 16 + g];      // broadcast
                u64 t0 = fadd2(kvr[g].x, qv.x) & ABSM;  // |k - q| (q pre-negated)
                u64 t1 = fadd2(kvr[g].y, qv.y) & ABSM;
                acc[q] = ffma2(dv.x, t0, acc[q]);
                acc[q] = ffma2(dv.y, t1, acc[q]);
            }
        }

        #pragma unroll
        for (int q = 0; q < 8; q++) {
            float2 a = upk2(acc[q]);
            float e = __expf((CENTER_C - (a.x + a.y)) * INV_SCALING_C);
            attn[arow0 + (size_t)(qg * 8 + q) * LK + c * 128 + kg * 32 + lane] = e;
            sume[q] += e;
        }
    }

    // softmax partial sums per (q, kg)
    #pragma unroll
    for (int q = 0; q < 8; q++) {
        float ssum = sume[q];
        #pragma unroll
        for (int o = 16; o > 0; o >>= 1) ssum += __shfl_xor_sync(0xffffffffu, ssum, o);
        if (lane == 0) part[(qg * 8 + q) * 4 + kg] = ssum;
    }
    __threadfence();                              // e STGs -> GPU scope
    asm volatile("fence.proxy.async;" ::: "memory");
    __syncthreads();
    if (tid < 16)
        invs[tid] = 1.f / (part[tid * 4] + part[tid * 4 + 1] +
                           part[tid * 4 + 2] + part[tid * 4 + 3]);

    // issue phase-2 chunk 0 into stage 0: V^T (64 x 512B, stride 528B) + e (16 x 512B)
    const float* vtb = g_VT + ((size_t)(b * NH + h)) * DD * LK;
    if (tid == 0) MBAR_EXPECT(mb0, 40960u);
    if (tid < 64)
        bulk_cp(sbase + (uint32_t)tid * 528u, vtb + (size_t)tid * LK, 512u, mb0);
    else if (tid < 80)
        bulk_cp(sbase + (uint32_t)(EOFF * 4 + (tid - 64) * 512),
                attn + arow0 + (size_t)(tid - 64) * LK, 512u, mb0);

    // ==== Phase 2: p write + P@V ==========================================
    u64 acc2[8][2];
    #pragma unroll
    for (int q = 0; q < 8; q++) { acc2[q][0] = 0ull; acc2[q][1] = 0ull; }

    for (int c = 0; c < NCH; c++) {
        int kc = c * 128;
        MBAR_WAIT((c & 1) ? mb1 : mb0, (c >> 1) & 1);   // uses 8..15 -> same parity seq
        __syncthreads();   // other stage free; invs visible on c==0

        if (c + 1 < NCH) {
            uint32_t mbn = ((c + 1) & 1) ? mb1 : mb0;
            uint32_t dstb = sbase + (uint32_t)(((c + 1) & 1) * STGF * 4);
            if (tid == 0) MBAR_EXPECT(mbn, 40960u);
            if (tid < 64)
                bulk_cp(dstb + (uint32_t)tid * 528u,
                        vtb + (size_t)tid * LK + kc + 128, 512u, mbn);
            else if (tid < 80)
                bulk_cp(dstb + (uint32_t)(EOFF * 4 + (tid - 64) * 512),
                        attn + arow0 + (size_t)(tid - 64) * LK + kc + 128, 512u, mbn);
        }

        const float* stg = smem + (c & 1) * STGF;
        const float* estg = stg + EOFF;

        // write p = e * inv (coalesced STG.128): 512 f4 by 256 threads
        #pragma unroll
        for (int r = 0; r < 2; r++) {
            int j = tid + NT * r; int qq = j >> 5, k4 = j & 31;
            float4 e4 = *(const float4*)(estg + qq * 128 + 4 * k4);
            float iv = invs[qq];
            float4 p = make_float4(e4.x * iv, e4.y * iv, e4.z * iv, e4.w * iv);
            *(float4*)(attn + arow0 + (size_t)qq * LK + kc + 4 * k4) = p;
        }

        // P@V: warp covers k-quarter (8 f4), 8 q rows; lane = d (two halves)
        #pragma unroll
        for (int k4i = 0; k4i < 8; k4i++) {
            int k4 = kg * 8 + k4i;
            ulonglong2 v0 = *(const ulonglong2*)(stg + lane * 132 + k4 * 4);
            ulonglong2 v1 = *(const ulonglong2*)(stg + (lane + 32) * 132 + k4 * 4);
            #pragma unroll
            for (int q = 0; q < 8; q++) {
                ulonglong2 pp = *(const ulonglong2*)(estg + (qg * 8 + q) * 128
                                                     + k4 * 4);   // broadcast
                acc2[q][0] = ffma2(pp.x, v0.x, acc2[q][0]);
                acc2[q][0] = ffma2(pp.y, v0.y, acc2[q][0]);
                acc2[q][1] = ffma2(pp.x, v1.x, acc2[q][1]);
                acc2[q][1] = ffma2(pp.y, v1.y, acc2[q][1]);
            }
        }
    }
    __syncthreads();    // all done with stage areas before reduce reuse

    // reduce k-quarter partials: red[4][16q][64d] in stage-0 area
    float* red = smem;
    #pragma unroll
    for (int q = 0; q < 8; q++) {
        float2 a0 = upk2(acc2[q][0]);
        float2 a1 = upk2(acc2[q][1]);
        red[kg * 1024 + (qg * 8 + q) * 64 + lane]      = a0.x + a0.y;
        red[kg * 1024 + (qg * 8 + q) * 64 + 32 + lane] = a1.x + a1.y;
    }
    __syncthreads();
    #pragma unroll
    for (int r = 0; r < 4; r++) {
        int j = tid + NT * r;                   // j = qq*64 + d
        int qq = j >> 6, d = j & 63;
        float v = red[j] + red[1024 + j] + red[2048 + j] + red[3072 + j];
        out0[((size_t)(b * LQ + q0 + qq)) * HIDD + h * DD + d] = v * invs[qq];
    }
}

extern "C" void kernel_launch(void* const* d_in, const int* in_sizes, int n_in,
                              void* d_out, int out_size)
{
    const float* Qg = (const float*)d_in[0];
    const float* Kg = (const float*)d_in[1];
    const float* Vg = (const float*)d_in[2];
    const float* dg = (const float*)d_in[3];

    float* out0 = (float*)d_out;
    float* attn = out0 + (size_t)BB * LQ * HIDD;   // (output, attention) concat

    cudaFuncSetAttribute(k_fused, cudaFuncAttributeMaxDynamicSharedMemorySize, SMEMF);

    k_vtrans<<<dim3(LK / 64, BB * NH), 256>>>(Vg);
    k_fused<<<dim3(LQ / QT, NH, BB), NT, SMEMF>>>(Qg, Kg, dg, attn, out0);
}

// round 11
// speedup vs baseline: 1.1068x; 1.1068x over previous
#include <cuda_runtime.h>
#include <cuda_bf16.h>
#include <cstdint>

#define BB    4
#define LQ    256
#define LK    2048
#define HIDD  1024
#define NH    16
#define DD    64
#define QT    16                     /* q rows per CTA */
#define NT    256                    /* threads per CTA */
#define NCH   16                     /* chunks of 128 k */

#define CENTER_C      72.21632f
#define INV_SCALING_C 0.14662718f

typedef unsigned long long u64;
#define ABSM 0x7FFFFFFF7FFFFFFFULL

__device__ float g_VT[(size_t)BB * NH * DD * LK];   // V transposed [b,h,d,k]
__device__ float g_rsum[BB * NH * LQ];              // 1/sum(exp) per q row

__device__ __forceinline__ u64 fadd2(u64 a, u64 b) {
    u64 r; asm("add.rn.f32x2 %0, %1, %2;" : "=l"(r) : "l"(a), "l"(b)); return r;
}
__device__ __forceinline__ u64 ffma2(u64 a, u64 b, u64 c) {
    u64 r; asm("fma.rn.f32x2 %0, %1, %2, %3;" : "=l"(r) : "l"(a), "l"(b), "l"(c)); return r;
}
__device__ __forceinline__ float2 upk2(u64 a) {
    float2 f; asm("mov.b64 {%0, %1}, %2;" : "=f"(f.x), "=f"(f.y) : "l"(a)); return f;
}
__device__ __forceinline__ void cp16(uint32_t dst, const void* src) {
    asm volatile("cp.async.cg.shared.global [%0], [%1], 16;" :: "r"(dst), "l"(src));
}

// ---------------------------------------------------------------------------
// Kernel 0: transpose V -> VT[b,h,d,k].
// ---------------------------------------------------------------------------
__global__ __launch_bounds__(256) void k_vtrans(const float* __restrict__ Vg)
{
    __shared__ float t[64][65];
    const int bh = blockIdx.y, b = bh >> 4, h = bh & 15;
    const int k0 = blockIdx.x * 64;
    const int tid = threadIdx.x;
    #pragma unroll
    for (int r = 0; r < 4; r++) {
        int i = tid + 256 * r; int kr = i >> 4, g = i & 15;
        float4 v = *(const float4*)(Vg + ((size_t)(b * LK + k0 + kr)) * HIDD + h * DD + 4 * g);
        t[kr][4 * g + 0] = v.x; t[kr][4 * g + 1] = v.y;
        t[kr][4 * g + 2] = v.z; t[kr][4 * g + 3] = v.w;
    }
    __syncthreads();
    #pragma unroll
    for (int r = 0; r < 4; r++) {
        int i = tid + 256 * r; int d = i >> 4, g = i & 15;
        float4 o = make_float4(t[4 * g + 0][d], t[4 * g + 1][d], t[4 * g + 2][d], t[4 * g + 3][d]);
        *(float4*)(g_VT + ((size_t)(bh * DD + d)) * LK + k0 + 4 * g) = o;
    }
}

// ---------------------------------------------------------------------------
// Kernel 1 (phase 1): L1 distance -> e (unnormalized) -> attn; 1/sum -> g_rsum.
//   grid (LQ/16, NH, BB), block 256, ~70KB smem -> 3 CTAs/SM.
//   Warp = kg (w&3: 32 k lanes) x qg (w>>2: 8 q rows); K rows register-resident
//   (two 8-reg halves to fit 84 regs); XOR-swizzled K staging, 2-stage ring.
//   SMEM floats: [0,16384) K ring (2 x 8192); [16384,17408) qbuf;
//                [17408,17472) dbuf; [17472,17536) part
// ---------------------------------------------------------------------------
__global__ __launch_bounds__(NT, 3) void k_dist(
    const float* __restrict__ Qg, const float* __restrict__ Kg,
    const float* __restrict__ diag, float* __restrict__ attn)
{
    extern __shared__ float smem[];
    float* qbuf = smem + 16384;
    float* dbuf = smem + 17408;
    float* part = smem + 17472;

    const int b  = blockIdx.z, h = blockIdx.y;
    const int q0 = blockIdx.x * QT;
    const int tid = threadIdx.x, w = tid >> 5, lane = tid & 31;
    const int kg = w & 3, qg = w >> 2;          // k-quarter (32k), 8 q rows
    const int s  = lane & 7;
    const uint32_t sbase = (uint32_t)__cvta_generic_to_shared(smem);

    const size_t arow0 = (((size_t)(b * NH + h)) * LQ + q0) * (size_t)LK;

    if (tid < 16)
        ((float4*)dbuf)[tid] = ((const float4*)(diag + h * DD))[tid];
    {
        int qr = tid >> 4, g = tid & 15;        // 16 rows x 16 f4, negated
        float4 v = ((const float4*)(Qg + ((size_t)(b * LQ + q0 + qr)) * HIDD + h * DD))[g];
        ((float4*)qbuf)[qr * 16 + g] = make_float4(-v.x, -v.y, -v.z, -v.w);
    }

    // prefetch K chunk 0 (XOR-swizzled f4 rows: 128 k-rows x 16 f4)
    #pragma unroll
    for (int r = 0; r < 8; r++) {
        int i = tid + NT * r; int kr = i >> 4, g = i & 15;
        cp16(sbase + (uint32_t)((kr * 16 + (g ^ (kr & 7))) * 16),
             ((const float4*)(Kg + ((size_t)(b * LK + kr)) * HIDD + h * DD)) + g);
    }
    asm volatile("cp.async.commit_group;");

    const ulonglong2* qb2 = (const ulonglong2*)qbuf;
    const ulonglong2* db2 = (const ulonglong2*)dbuf;
    float sume[8] = {0.f, 0.f, 0.f, 0.f, 0.f, 0.f, 0.f, 0.f};
    const int krow16 = (kg * 32 + lane) * 16;

    for (int c = 0; c < NCH; c++) {
        asm volatile("cp.async.wait_group 0;");
        __syncthreads();          // buf[c&1] full; everyone done with buf[(c+1)&1]

        if (c + 1 < NCH) {
            uint32_t boff = (uint32_t)(((c + 1) & 1) * 32768);
            #pragma unroll
            for (int r = 0; r < 8; r++) {
                int i = tid + NT * r; int kr = i >> 4, g = i & 15;
                cp16(sbase + boff + (uint32_t)((kr * 16 + (g ^ (kr & 7))) * 16),
                     ((const float4*)(Kg + ((size_t)(b * LK + (c + 1) * 128 + kr)) * HIDD
                                      + h * DD)) + g);
            }
            asm volatile("cp.async.commit_group;");
        }

        const ulonglong2* kb2 = (const ulonglong2*)(smem + (c & 1) * 8192);

        u64 acc[8];
        #pragma unroll
        for (int q = 0; q < 8; q++) acc[q] = 0ull;

        // two half-passes over d to keep kvr at 8 regs (occ-3 register budget)
        #pragma unroll
        for (int gh = 0; gh < 2; gh++) {
            ulonglong2 kvr[8];
            #pragma unroll
            for (int gi = 0; gi < 8; gi++)
                kvr[gi] = kb2[krow16 + ((gh * 8 + gi) ^ s)];
            #pragma unroll
            for (int gi = 0; gi < 8; gi++) {
                int g = gh * 8 + gi;
                ulonglong2 dv = db2[g];                          // broadcast
                #pragma unroll
                for (int q = 0; q < 8; q++) {
                    ulonglong2 qv = qb2[(qg * 8 + q) * 16 + g];  // broadcast
                    u64 t0 = fadd2(kvr[gi].x, qv.x) & ABSM;  // |k-q| (q pre-negated)
                    u64 t1 = fadd2(kvr[gi].y, qv.y) & ABSM;
                    acc[q] = ffma2(dv.x, t0, acc[q]);
                    acc[q] = ffma2(dv.y, t1, acc[q]);
                }
            }
        }

        #pragma unroll
        for (int q = 0; q < 8; q++) {
            float2 a = upk2(acc[q]);
            float e = __expf((CENTER_C - (a.x + a.y)) * INV_SCALING_C);
            attn[arow0 + (size_t)(qg * 8 + q) * LK + c * 128 + kg * 32 + lane] = e;
            sume[q] += e;
        }
    }

    #pragma unroll
    for (int q = 0; q < 8; q++) {
        float ssum = sume[q];
        #pragma unroll
        for (int o = 16; o > 0; o >>= 1) ssum += __shfl_xor_sync(0xffffffffu, ssum, o);
        if (lane == 0) part[(qg * 8 + q) * 4 + kg] = ssum;
    }
    __syncthreads();
    if (tid < 16)
        g_rsum[((size_t)(b * NH + h)) * LQ + q0 + tid] =
            1.f / (part[tid * 4] + part[tid * 4 + 1] +
                   part[tid * 4 + 2] + part[tid * 4 + 3]);
}

// ---------------------------------------------------------------------------
// Kernel 2 (phase 2): p = e * inv -> attn; P@V -> out. (R8 phase-2 verbatim.)
//   grid (LQ/16, NH, BB), block 256, ~82KB smem -> 2 CTAs/SM.
//   SMEM floats: [0,16384) V^T ring (2 x 8192, XOR swizzled);
//                [16384,20480) e-stage ring (2 x 2048); [20480,20496) invs
// ---------------------------------------------------------------------------
__global__ __launch_bounds__(NT, 2) void k_pv(
    float* __restrict__ attn, float* __restrict__ out0)
{
    extern __shared__ float smem[];
    float* estg0 = smem + 16384;
    float* invs  = smem + 20480;

    const int b  = blockIdx.z, h = blockIdx.y;
    const int q0 = blockIdx.x * QT;
    const int tid = threadIdx.x, w = tid >> 5, lane = tid & 31;
    const int kg = w & 3, qg = w >> 2;
    const int s  = lane & 7;
    const uint32_t sbase = (uint32_t)__cvta_generic_to_shared(smem);
    const uint32_t estg_b = sbase + 16384u * 4u;

    const size_t arow0 = (((size_t)(b * NH + h)) * LQ + q0) * (size_t)LK;
    const float* vtb = g_VT + ((size_t)(b * NH + h)) * DD * LK;

    if (tid < 16) invs[tid] = g_rsum[((size_t)(b * NH + h)) * LQ + q0 + tid];

    // prefetch V^T chunk 0 + e chunk 0
    #pragma unroll
    for (int r = 0; r < 8; r++) {
        int j = tid + NT * r; int d = j >> 5, k4 = j & 31;
        cp16(sbase + (uint32_t)((d * 32 + (k4 ^ (d & 7))) * 16),
             vtb + (size_t)d * LK + 4 * k4);
    }
    #pragma unroll
    for (int r = 0; r < 2; r++) {
        int j = tid + NT * r; int qq = j >> 5, k4 = j & 31;
        cp16(estg_b + (uint32_t)(j * 16),
             attn + arow0 + (size_t)qq * LK + 4 * k4);
    }
    asm volatile("cp.async.commit_group;");

    u64 acc2[8][2];
    #pragma unroll
    for (int q = 0; q < 8; q++) { acc2[q][0] = 0ull; acc2[q][1] = 0ull; }

    for (int c = 0; c < NCH; c++) {
        int kc = c * 128;
        if (c + 1 < NCH) {
            uint32_t boff  = (uint32_t)(((c + 1) & 1) * 32768);
            uint32_t boffe = (uint32_t)(((c + 1) & 1) * 8192);
            #pragma unroll
            for (int r = 0; r < 8; r++) {
                int j = tid + NT * r; int d = j >> 5, k4 = j & 31;
                cp16(sbase + boff + (uint32_t)((d * 32 + (k4 ^ (d & 7))) * 16),
                     vtb + (size_t)d * LK + kc + 128 + 4 * k4);
            }
            #pragma unroll
            for (int r = 0; r < 2; r++) {
                int j = tid + NT * r; int qq = j >> 5, k4 = j & 31;
                cp16(estg_b + boffe + (uint32_t)(j * 16),
                     attn + arow0 + (size_t)qq * LK + kc + 128 + 4 * k4);
            }
            asm volatile("cp.async.commit_group;");
            asm volatile("cp.async.wait_group 1;");
        } else {
            asm volatile("cp.async.wait_group 0;");
        }
        __syncthreads();   // stage[c&1] ready; invs visible on c==0

        const float* estg = estg0 + (c & 1) * 2048;

        // write p = e * inv (coalesced STG.128)
        #pragma unroll
        for (int r = 0; r < 2; r++) {
            int j = tid + NT * r; int qq = j >> 5, k4 = j & 31;
            float4 e4 = *(const float4*)(estg + j * 4);
            float iv = invs[qq];
            float4 p = make_float4(e4.x * iv, e4.y * iv, e4.z * iv, e4.w * iv);
            *(float4*)(attn + arow0 + (size_t)qq * LK + kc + 4 * k4) = p;
        }

        // P@V: warp covers k-quarter (8 f4), 8 q rows; lane = d (two halves)
        const float4* vb4 = ((const float4*)smem) + (c & 1) * 2048;
        #pragma unroll
        for (int k4i = 0; k4i < 8; k4i++) {
            int kidx4 = kg * 8 + k4i;
            int sw = kidx4 ^ s;
            ulonglong2 v0 = *(const ulonglong2*)&vb4[lane * 32 + sw];
            ulonglong2 v1 = *(const ulonglong2*)&vb4[(lane + 32) * 32 + sw];
            #pragma unroll
            for (int q = 0; q < 8; q++) {
                ulonglong2 pp = *(const ulonglong2*)(estg + (qg * 8 + q) * 128
                                                     + kidx4 * 4);   // broadcast
                acc2[q][0] = ffma2(pp.x, v0.x, acc2[q][0]);
                acc2[q][0] = ffma2(pp.y, v0.y, acc2[q][0]);
                acc2[q][1] = ffma2(pp.x, v1.x, acc2[q][1]);
                acc2[q][1] = ffma2(pp.y, v1.y, acc2[q][1]);
            }
        }
        __syncthreads();
    }

    // reduce k-quarter partials: red[4][16q][64d] in ring area
    float* red = smem;
    #pragma unroll
    for (int q = 0; q < 8; q++) {
        float2 a0 = upk2(acc2[q][0]);
        float2 a1 = upk2(acc2[q][1]);
        red[kg * 1024 + (qg * 8 + q) * 64 + lane]      = a0.x + a0.y;
        red[kg * 1024 + (qg * 8 + q) * 64 + 32 + lane] = a1.x + a1.y;
    }
    __syncthreads();
    #pragma unroll
    for (int r = 0; r < 4; r++) {
        int j = tid + NT * r;                   // j = qq*64 + d
        int qq = j >> 6, d = j & 63;
        float v = red[j] + red[1024 + j] + red[2048 + j] + red[3072 + j];
        out0[((size_t)(b * LQ + q0 + qq)) * HIDD + h * DD + d] = v * invs[qq];
    }
}

#define SMEM1 (17536 * 4)    /* 70144 B -> 3 CTAs/SM */
#define SMEM2 (20496 * 4)    /* 81984 B -> 2 CTAs/SM */

extern "C" void kernel_launch(void* const* d_in, const int* in_sizes, int n_in,
                              void* d_out, int out_size)
{
    const float* Qg = (const float*)d_in[0];
    const float* Kg = (const float*)d_in[1];
    const float* Vg = (const float*)d_in[2];
    const float* dg = (const float*)d_in[3];

    float* out0 = (float*)d_out;
    float* attn = out0 + (size_t)BB * LQ * HIDD;   // (output, attention) concat

    cudaFuncSetAttribute(k_dist, cudaFuncAttributeMaxDynamicSharedMemorySize, SMEM1);
    cudaFuncSetAttribute(k_pv,   cudaFuncAttributeMaxDynamicSharedMemorySize, SMEM2);

    dim3 grid(LQ / QT, NH, BB);
    k_vtrans<<<dim3(LK / 64, BB * NH), 256>>>(Vg);
    k_dist<<<grid, NT, SMEM1>>>(Qg, Kg, dg, attn);
    k_pv<<<grid, NT, SMEM2>>>(attn, out0);
}